// round 12
// baseline (speedup 1.0000x reference)
#include <cuda_runtime.h>
#include <cuda_bf16.h>
#include <cuda_fp16.h>
#include <cstdint>

// Problem dims
#define NB   8
#define SQ   1024
#define EE   1024
#define HH   16
#define DK   64

// -------------------- scratch (static device arrays; no allocation) -----------
__device__ unsigned long long g_maskb[NB * SQ * 16];   // bit-packed, [n][kt][qrow]
__device__ int g_mask_fmt;

__device__ __half g_xf[NB * SQ * EE];            // x fp16
__device__ __half g_wth[4 * EE * EE];            // W^T fp16, [n][k], 4 mats
__device__ __half g_qf[NB * HH * SQ * DK];       // [n,h,s,d] fp16 (pre-scaled by SCL2)
__device__ __half g_kf[NB * HH * SQ * DK];
__device__ __half g_vf[NB * HH * SQ * DK];
__device__ __half g_aof[NB * SQ * EE];           // attn-out fp16, [n,s,e]

#define SCL2 0.1803368801111244f   // 0.125 * log2(e)

// -------------------- helpers --------------------------------------------------
__device__ __forceinline__ uint32_t smem_u32(const void* p) {
    uint32_t a;
    asm("{ .reg .u64 t; cvta.to.shared.u64 t, %1; cvt.u32.u64 %0, t; }" : "=r"(a) : "l"(p));
    return a;
}
__device__ __forceinline__ void cp_async16(uint32_t dst, const void* src) {
    asm volatile("cp.async.cg.shared.global [%0], [%1], 16;" :: "r"(dst), "l"(src));
}
#define CP_COMMIT() asm volatile("cp.async.commit_group;" ::: "memory")
#define CP_WAIT1()  asm volatile("cp.async.wait_group 1;" ::: "memory")
#define CP_WAIT0()  asm volatile("cp.async.wait_group 0;" ::: "memory")

__device__ __forceinline__ void ldsm4(uint32_t* r, uint32_t addr) {
    asm volatile("ldmatrix.sync.aligned.m8n8.x4.shared.b16 {%0,%1,%2,%3}, [%4];"
        : "=r"(r[0]), "=r"(r[1]), "=r"(r[2]), "=r"(r[3]) : "r"(addr));
}
__device__ __forceinline__ void ldsm4t(uint32_t* r, uint32_t addr) {
    asm volatile("ldmatrix.sync.aligned.m8n8.x4.trans.shared.b16 {%0,%1,%2,%3}, [%4];"
        : "=r"(r[0]), "=r"(r[1]), "=r"(r[2]), "=r"(r[3]) : "r"(addr));
}
__device__ __forceinline__ void mma_f16(float* c, const uint32_t* a, uint32_t b0, uint32_t b1) {
    asm volatile(
        "mma.sync.aligned.m16n8k16.row.col.f32.f16.f16.f32 "
        "{%0,%1,%2,%3}, {%4,%5,%6,%7}, {%8,%9}, {%0,%1,%2,%3};"
        : "+f"(c[0]), "+f"(c[1]), "+f"(c[2]), "+f"(c[3])
        : "r"(a[0]), "r"(a[1]), "r"(a[2]), "r"(a[3]), "r"(b0), "r"(b1));
}
__device__ __forceinline__ uint32_t pack_f16(float x, float y) {
    __half2 t = __floats2half2_rn(x, y);
    return *(uint32_t*)&t;
}

// -------------------- mask dtype detection ------------------------------------
__global__ void detect_mask_kernel(const unsigned int* __restrict__ m) {
    __shared__ int s01, sf;
    if (threadIdx.x == 0) { s01 = 1; sf = 1; }
    __syncthreads();
    unsigned int v = m[threadIdx.x];
    if (v > 1u) s01 = 0;
    if (v != 0u && v != 0x3F800000u) sf = 0;
    __syncthreads();
    if (threadIdx.x == 0) g_mask_fmt = s01 ? 0 : (sf ? 1 : 2);
}

// -------------------- fused prep: tohalf + W^T convert + mask bit-pack ---------
// blocks [0, 8192)            : x -> fp16           (256 thr, 1 float4/thread)
// blocks [8192, 12288)        : W -> W^T fp16       (flattened 32x8 layout)
// blocks [12288, 28672)       : mask -> bit-pack    (8 warps/block)
#define PREP_GRID 28672

__global__ void prep_kernel(
    const float* __restrict__ x, __half* __restrict__ xf,
    const float* __restrict__ W0, const float* __restrict__ W1,
    const float* __restrict__ W2, const float* __restrict__ W3,
    __half* __restrict__ wth,
    const void* __restrict__ m, unsigned long long* __restrict__ mout)
{
    __shared__ float t[32][33];
    const int b = blockIdx.x;
    const int tid = threadIdx.x;

    if (b < 8192) {
        int i = b * 256 + tid;
        float4 v = ((const float4*)x)[i];
        __half2* o2 = (__half2*)xf;
        o2[i * 2]     = __floats2half2_rn(v.x, v.y);
        o2[i * 2 + 1] = __floats2half2_rn(v.z, v.w);
    } else if (b < 12288) {
        int bb = b - 8192;
        int z = bb >> 10, rem = bb & 1023;
        int by = rem >> 5, bx = rem & 31;
        const float* W = (z == 0) ? W0 : (z == 1) ? W1 : (z == 2) ? W2 : W3;
        int tx = tid & 31, ty = tid >> 5;          // 32 x 8
        int k0 = by * 32, n0 = bx * 32;
#pragma unroll
        for (int j = 0; j < 4; j++)
            t[ty + 8 * j][tx] = W[(size_t)(k0 + ty + 8 * j) * EE + n0 + tx];
        __syncthreads();
        size_t off = (size_t)z << 20;
#pragma unroll
        for (int j = 0; j < 4; j++)
            wth[off + (size_t)(n0 + ty + 8 * j) * EE + k0 + tx] =
                __float2half(t[tx][ty + 8 * j]);
    } else {
        int gw = (b - 12288) * 8 + (tid >> 5);
        int lane = tid & 31;
        int n = gw >> 14;
        int rem = gw & 16383;
        int qrow = rem >> 4;
        int kt = rem & 15;
        size_t base = ((size_t)(n * SQ + qrow)) * SQ + kt * 64;
        int fmt = g_mask_fmt;
        unsigned a, bb;
        if (fmt == 2) {
            const unsigned char* p = (const unsigned char*)m + base;
            a = (p[lane] != 0); bb = (p[lane + 32] != 0);
        } else {
            const unsigned* p = (const unsigned*)m + base;
            unsigned va = p[lane], vb = p[lane + 32];
            if (fmt == 1) { va &= 0x7fffffffu; vb &= 0x7fffffffu; }
            a = (va != 0); bb = (vb != 0);
        }
        unsigned lo = __ballot_sync(0xffffffffu, a);
        unsigned hi = __ballot_sync(0xffffffffu, bb);
        if (lane == 0)
            mout[((size_t)(n * 16 + kt)) * SQ + qrow] =
                ((unsigned long long)hi << 32) | lo;
    }
}

// -------------------- single-product fp16 GEMM (KC=32, 2 CTAs/SM) --------------
#define TSZ        8192
#define STAGE_B    (2 * TSZ)      // 16KB
#define GEMM_SMEM  (3 * STAGE_B)  // 48KB
#define NKC        32

__device__ __forceinline__ void load_stage(
    uint32_t sb, const __half* af, const __half* bh, int kc, int tid)
{
    const __half* bases[2] = {af, bh};
#pragma unroll
    for (int t2 = 0; t2 < 2; t2++) {
        const __half* base = bases[t2] + kc * 32;
        uint32_t dtile = sb + t2 * TSZ;
#pragma unroll
        for (int p = 0; p < 2; p++) {
            int idx = p * 256 + tid;
            int r = idx >> 2, c = idx & 3;
            cp_async16(dtile + r * 64 + ((c ^ ((r >> 1) & 3)) << 4),
                       base + (size_t)r * EE + c * 8);
        }
    }
}

__global__ void __launch_bounds__(256, 2) gemm_mma_kernel(
    const __half* __restrict__ Af, const __half* __restrict__ Wh,
    const float* __restrict__ b0, const float* __restrict__ b1, const float* __restrict__ b2,
    float* fo, __half* f0, __half* f1, __half* f2,
    float s0, float s1, float s2,
    int headmajor, int wbase)
{
    extern __shared__ char smem[];
    const uint32_t sbase = smem_u32(smem);
    const int tid = threadIdx.x;
    const int z = blockIdx.z;
    const float* bias = (z == 0) ? b0 : (z == 1) ? b1 : b2;
    __half* hf = (z == 0) ? f0 : (z == 1) ? f1 : f2;
    const float osc = (z == 0) ? s0 : (z == 1) ? s1 : s2;
    const size_t woff = ((size_t)(wbase + z)) << 20;

    const int mBase = blockIdx.y * 128;
    const int nBase = blockIdx.x * 128;
    const __half* af = Af + (size_t)mBase * EE;
    const __half* bh = Wh + woff + (size_t)nBase * EE;

    load_stage(sbase + 0 * STAGE_B, af, bh, 0, tid);
    CP_COMMIT();
    load_stage(sbase + 1 * STAGE_B, af, bh, 1, tid);
    CP_COMMIT();

    const int lane = tid & 31;
    const int wm = (tid >> 5) & 1;
    const int wn = tid >> 6;
    const int l15 = lane & 15, l16 = lane >> 4;

    float c[4][4][4];
#pragma unroll
    for (int i = 0; i < 4; i++)
#pragma unroll
        for (int j = 0; j < 4; j++)
#pragma unroll
            for (int q = 0; q < 4; q++) c[i][j][q] = 0.0f;

    for (int kc = 0; kc < NKC; kc++) {
        CP_WAIT1();
        __syncthreads();
        if (kc + 2 < NKC)
            load_stage(sbase + ((kc + 2) % 3) * STAGE_B, af, bh, kc + 2, tid);
        CP_COMMIT();

        const uint32_t sb = sbase + (kc % 3) * STAGE_B;
#pragma unroll
        for (int ko = 0; ko < 2; ko++) {
            uint32_t a[4][4], bh0[4], bh1[4];
            const int ch = ko * 2 + l16;
#pragma unroll
            for (int i = 0; i < 4; i++) {
                int r = wm * 64 + i * 16 + l15;
                ldsm4(a[i], sb + r * 64 + ((ch ^ ((r >> 1) & 3)) << 4));
            }
            {
                int r0 = wn * 32 + l15;
                int r1 = wn * 32 + 16 + l15;
                ldsm4(bh0, sb + TSZ + r0 * 64 + ((ch ^ ((r0 >> 1) & 3)) << 4));
                ldsm4(bh1, sb + TSZ + r1 * 64 + ((ch ^ ((r1 >> 1) & 3)) << 4));
            }
#pragma unroll
            for (int i = 0; i < 4; i++) {
                mma_f16(c[i][0], a[i], bh0[0], bh0[2]);
                mma_f16(c[i][1], a[i], bh0[1], bh0[3]);
                mma_f16(c[i][2], a[i], bh1[0], bh1[2]);
                mma_f16(c[i][3], a[i], bh1[1], bh1[3]);
            }
        }
    }

    const int lr = lane >> 2, lc = lane & 3;
#pragma unroll
    for (int i = 0; i < 4; i++) {
#pragma unroll
        for (int half = 0; half < 2; half++) {
            const int R = mBase + wm * 64 + i * 16 + half * 8 + lr;
#pragma unroll
            for (int j = 0; j < 4; j++) {
                const int C0 = nBase + wn * 32 + j * 8 + lc * 2;
                float2 bv = *(const float2*)(bias + C0);
                float vx = (c[i][j][half * 2 + 0] + bv.x) * osc;
                float vy = (c[i][j][half * 2 + 1] + bv.y) * osc;
                if (headmajor) {
                    const int nidx = R >> 10, sidx = R & 1023;
                    const int head = C0 >> 6, dd = C0 & 63;
                    size_t off = (((size_t)(nidx * HH + head) * SQ + sidx) << 6) + dd;
                    *(__half2*)(hf + off) = __floats2half2_rn(vx, vy);
                } else {
                    *(float2*)(fo + (size_t)R * EE + C0) = make_float2(vx, vy);
                }
            }
        }
    }
}

// -------------------- flash attention, fp16 mma --------------------------------
// CTA: 128 q-rows x 1 head; 8 warps x 16 rows; kv tiles of 64.
// Q is pre-scaled by SCL2 -> logits arrive in log2 domain.
#define A_ST0    16384
#define A_STG    17408
#define A_V      8192
#define A_MB     16384
#define ATT_SMEM (A_ST0 + 2 * A_STG)

__device__ __forceinline__ void att_load_stage(
    uint32_t sb, int st, const __half* kf, const __half* vf,
    const unsigned long long* mb, int kt, int tid)
{
    const uint32_t dtile = sb + A_ST0 + st * A_STG;
    const __half* kb = kf + (size_t)kt * 64 * DK;
    const __half* vb = vf + (size_t)kt * 64 * DK;
#pragma unroll
    for (int p = 0; p < 2; p++) {
        int idx = p * 256 + tid;
        int r = idx >> 3, c = idx & 7;
        uint32_t sw = r * 128 + ((c ^ (r & 7)) << 4);
        cp_async16(dtile + sw, kb + r * 64 + c * 8);
        cp_async16(dtile + A_V + sw, vb + r * 64 + c * 8);
    }
    if (tid < 64)
        cp_async16(dtile + A_MB + tid * 16, mb + (size_t)kt * SQ + tid * 2);
}

__global__ void __launch_bounds__(256, 2) attn_mma_kernel(
    const __half* __restrict__ Qf, const __half* __restrict__ Kf,
    const __half* __restrict__ Vf,
    const unsigned long long* __restrict__ maskb,
    __half* __restrict__ Of)
{
    extern __shared__ char smem[];
    const uint32_t sb = smem_u32(smem);
    const int tid = threadIdx.x;
    const int qt = blockIdx.x, h = blockIdx.y, n = blockIdx.z;

    const size_t hoff = (size_t)(n * HH + h) * SQ * DK;
    const __half* qf = Qf + hoff + (size_t)qt * 128 * DK;
    const __half* kf = Kf + hoff;
    const __half* vf = Vf + hoff;
    const unsigned long long* mb = maskb + (size_t)n * 16 * SQ + qt * 128;

    // Q load (group 0, with stage 0)
#pragma unroll
    for (int p = 0; p < 4; p++) {
        int idx = p * 256 + tid;
        int r = idx >> 3, c = idx & 7;
        cp_async16(sb + r * 128 + ((c ^ (r & 7)) << 4), qf + r * 64 + c * 8);
    }
    att_load_stage(sb, 0, kf, vf, mb, 0, tid);
    CP_COMMIT();

    const int w = tid >> 5, lane = tid & 31;
    const int l15 = lane & 15, l16 = lane >> 4;
    const int lr = lane >> 2, lc = lane & 3;
    const int row0 = w * 16 + lr;
    const int qg0 = qt * 128 + row0;
    const int qg1 = qg0 + 8;

    CP_WAIT0();
    __syncthreads();

    // hoist Q fragments for the whole loop (16 regs)
    uint32_t aq[4][4];
#pragma unroll
    for (int ko = 0; ko < 4; ko++) {
        int r = w * 16 + l15;
        int ch = 2 * ko + l16;
        ldsm4(aq[ko], sb + r * 128 + ((ch ^ (r & 7)) << 4));
    }

    float o[8][4];
#pragma unroll
    for (int i = 0; i < 8; i++)
#pragma unroll
        for (int j = 0; j < 4; j++) o[i][j] = 0.0f;
    float m0 = -1e30f, m1 = -1e30f, l0 = 0.0f, l1 = 0.0f;

    for (int kt = 0; kt < 16; kt++) {
        // prefetch next tile into the other buffer
        if (kt + 1 < 16)
            att_load_stage(sb, (kt + 1) & 1, kf, vf, mb, kt + 1, tid);
        CP_COMMIT();

        const uint32_t stg = sb + A_ST0 + (kt & 1) * A_STG;
        const char* msp = smem + (A_ST0 + (kt & 1) * A_STG + A_MB);

        // ---- S = Q K^T (log2 domain; Q pre-scaled) ----
        float s[8][4];
#pragma unroll
        for (int i = 0; i < 8; i++)
#pragma unroll
            for (int j = 0; j < 4; j++) s[i][j] = 0.0f;

#pragma unroll
        for (int ko = 0; ko < 4; ko++) {
            const int ch = 2 * ko + l16;
#pragma unroll
            for (int nt2 = 0; nt2 < 4; nt2++) {
                int rk = nt2 * 16 + l15;
                uint32_t kb[4];
                ldsm4(kb, stg + rk * 128 + ((ch ^ (rk & 7)) << 4));
                mma_f16(s[2 * nt2],     aq[ko], kb[0], kb[2]);
                mma_f16(s[2 * nt2 + 1], aq[ko], kb[1], kb[3]);
            }
        }

        // ---- mask from bit-packed smem ----
        unsigned long long mr0 = *(const unsigned long long*)(msp + row0 * 8);
        unsigned long long mr1 = *(const unsigned long long*)(msp + (row0 + 8) * 8);
#pragma unroll
        for (int nt = 0; nt < 8; nt++) {
            const int c0 = nt * 8 + 2 * lc;
            if ((mr0 >> c0) & 1)       s[nt][0] = -1e9f;
            if ((mr0 >> (c0 + 1)) & 1) s[nt][1] = -1e9f;
            if ((mr1 >> c0) & 1)       s[nt][2] = -1e9f;
            if ((mr1 >> (c0 + 1)) & 1) s[nt][3] = -1e9f;
        }

        // ---- online softmax (base-2), warp-uniform rescale skip ----
        float vx0 = -1e30f, vx1 = -1e30f;
#pragma unroll
        for (int nt = 0; nt < 8; nt++) {
            vx0 = fmaxf(vx0, fmaxf(s[nt][0], s[nt][1]));
            vx1 = fmaxf(vx1, fmaxf(s[nt][2], s[nt][3]));
        }
        vx0 = fmaxf(vx0, __shfl_xor_sync(0xffffffffu, vx0, 1));
        vx0 = fmaxf(vx0, __shfl_xor_sync(0xffffffffu, vx0, 2));
        vx1 = fmaxf(vx1, __shfl_xor_sync(0xffffffffu, vx1, 1));
        vx1 = fmaxf(vx1, __shfl_xor_sync(0xffffffffu, vx1, 2));

        const unsigned upd = __ballot_sync(0xffffffffu, (vx0 > m0) || (vx1 > m1));
        float a0 = 1.0f, a1 = 1.0f;
        if (upd) {
            float mn0 = fmaxf(m0, vx0), mn1 = fmaxf(m1, vx1);
            a0 = exp2f(m0 - mn0); a1 = exp2f(m1 - mn1);
            m0 = mn0; m1 = mn1;
        }

        float sum0 = 0.0f, sum1 = 0.0f;
#pragma unroll
        for (int nt = 0; nt < 8; nt++) {
            s[nt][0] = exp2f(s[nt][0] - m0);
            s[nt][1] = exp2f(s[nt][1] - m0);
            s[nt][2] = exp2f(s[nt][2] - m1);
            s[nt][3] = exp2f(s[nt][3] - m1);
            sum0 += s[nt][0] + s[nt][1];
            sum1 += s[nt][2] + s[nt][3];
        }
        sum0 += __shfl_xor_sync(0xffffffffu, sum0, 1);
        sum0 += __shfl_xor_sync(0xffffffffu, sum0, 2);
        sum1 += __shfl_xor_sync(0xffffffffu, sum1, 1);
        sum1 += __shfl_xor_sync(0xffffffffu, sum1, 2);

        if (upd) {
            l0 = l0 * a0 + sum0;
            l1 = l1 * a1 + sum1;
#pragma unroll
            for (int nt = 0; nt < 8; nt++) {
                o[nt][0] *= a0; o[nt][1] *= a0;
                o[nt][2] *= a1; o[nt][3] *= a1;
            }
        } else {
            l0 += sum0;
            l1 += sum1;
        }

        // ---- O += P V ----
#pragma unroll
        for (int t = 0; t < 4; t++) {
            uint32_t ph[4];
            ph[0] = pack_f16(s[2 * t][0],     s[2 * t][1]);
            ph[1] = pack_f16(s[2 * t][2],     s[2 * t][3]);
            ph[2] = pack_f16(s[2 * t + 1][0], s[2 * t + 1][1]);
            ph[3] = pack_f16(s[2 * t + 1][2], s[2 * t + 1][3]);
#pragma unroll
            for (int dt2 = 0; dt2 < 4; dt2++) {
                int rv = t * 16 + l15;
                int chd = 2 * dt2 + l16;
                uint32_t vb[4];
                ldsm4t(vb, stg + A_V + rv * 128 + ((chd ^ (rv & 7)) << 4));
                mma_f16(o[2 * dt2],     ph, vb[0], vb[1]);
                mma_f16(o[2 * dt2 + 1], ph, vb[2], vb[3]);
            }
        }

        if (kt + 1 < 16) {
            CP_WAIT0();       // drain prefetch for kt+1
            __syncthreads();  // all warps done with current buffer
        }
    }

    // ---- epilogue: normalize, store fp16 [n,s,e] ----
    const float inv0 = 1.0f / l0, inv1 = 1.0f / l1;
    const size_t base0 = ((size_t)n * SQ + qg0) * EE + h * DK + 2 * lc;
    const size_t base1 = ((size_t)n * SQ + qg1) * EE + h * DK + 2 * lc;
#pragma unroll
    for (int nt = 0; nt < 8; nt++) {
        *(__half2*)(Of + base0 + nt * 8) =
            __floats2half2_rn(o[nt][0] * inv0, o[nt][1] * inv0);
        *(__half2*)(Of + base1 + nt * 8) =
            __floats2half2_rn(o[nt][2] * inv1, o[nt][3] * inv1);
    }
}

// -------------------- launch ---------------------------------------------------
extern "C" void kernel_launch(void* const* d_in, const int* in_sizes, int n_in,
                              void* d_out, int out_size)
{
    const float* x    = (const float*)d_in[0];
    const void*  mask = d_in[1];
    const float* Wq   = (const float*)d_in[2];
    const float* bq   = (const float*)d_in[3];
    const float* Wk   = (const float*)d_in[4];
    const float* bk   = (const float*)d_in[5];
    const float* Wv   = (const float*)d_in[6];
    const float* bv   = (const float*)d_in[7];
    const float* Wo   = (const float*)d_in[8];
    const float* bo   = (const float*)d_in[9];
    float* out = (float*)d_out;

    unsigned long long* mb;
    cudaGetSymbolAddress((void**)&mb, g_maskb);
    __half *xf, *wth, *qf, *kf, *vf, *aof;
    cudaGetSymbolAddress((void**)&xf,  g_xf);
    cudaGetSymbolAddress((void**)&wth, g_wth);
    cudaGetSymbolAddress((void**)&qf,  g_qf);
    cudaGetSymbolAddress((void**)&kf,  g_kf);
    cudaGetSymbolAddress((void**)&vf,  g_vf);
    cudaGetSymbolAddress((void**)&aof, g_aof);

    cudaFuncSetAttribute(gemm_mma_kernel,
                         cudaFuncAttributeMaxDynamicSharedMemorySize, GEMM_SMEM);
    cudaFuncSetAttribute(attn_mma_kernel,
                         cudaFuncAttributeMaxDynamicSharedMemorySize, ATT_SMEM);

    // 1. mask dtype detect
    detect_mask_kernel<<<1, 256>>>((const unsigned int*)mask);

    // 2. fused prep: x->fp16, W->W^T fp16, mask->bits
    prep_kernel<<<PREP_GRID, 256>>>(x, xf, Wq, Wk, Wv, Wo, wth, mask, mb);

    // 3. QKV projections -> fp16 head-major (Q pre-scaled by SCL2)
    gemm_mma_kernel<<<dim3(EE / 128, NB * SQ / 128, 3), 256, GEMM_SMEM>>>(
        xf, wth, bq, bk, bv, nullptr, qf, kf, vf,
        SCL2, 1.0f, 1.0f, 1, 0);

    // 4. flash attention (fp16 tensor cores) -> fp16 [n,s,e]
    attn_mma_kernel<<<dim3(SQ / 128, HH, NB), 256, ATT_SMEM>>>(
        qf, kf, vf, mb, aof);

    // 5. out projection -> f32 out
    gemm_mma_kernel<<<dim3(EE / 128, NB * SQ / 128, 1), 256, GEMM_SMEM>>>(
        aof, wth, bo, bo, bo, out,
        nullptr, nullptr, nullptr, 1.0f, 1.0f, 1.0f, 0, 3);
}

// round 13
// speedup vs baseline: 1.0944x; 1.0944x over previous
#include <cuda_runtime.h>
#include <cuda_bf16.h>
#include <cuda_fp16.h>
#include <cstdint>

// Problem dims
#define NB   8
#define SQ   1024
#define EE   1024
#define HH   16
#define DK   64

// -------------------- scratch (static device arrays; no allocation) -----------
__device__ unsigned long long g_maskb[NB * SQ * 16];   // bit-packed, [n][kt][qrow]
__device__ int g_mask_fmt;

__device__ __half g_xf[NB * SQ * EE];            // x fp16
__device__ __half g_wth[4 * EE * EE];            // W^T fp16, [n][k], 4 mats
__device__ __half g_qf[NB * HH * SQ * DK];       // [n,h,s,d] fp16 (pre-scaled by SCL2)
__device__ __half g_kf[NB * HH * SQ * DK];
__device__ __half g_vf[NB * HH * SQ * DK];
__device__ __half g_aof[NB * SQ * EE];           // attn-out fp16, [n,s,e]

#define SCL2 0.1803368801111244f   // 0.125 * log2(e)

// -------------------- helpers --------------------------------------------------
__device__ __forceinline__ uint32_t smem_u32(const void* p) {
    uint32_t a;
    asm("{ .reg .u64 t; cvta.to.shared.u64 t, %1; cvt.u32.u64 %0, t; }" : "=r"(a) : "l"(p));
    return a;
}
__device__ __forceinline__ void cp_async16(uint32_t dst, const void* src) {
    asm volatile("cp.async.cg.shared.global [%0], [%1], 16;" :: "r"(dst), "l"(src));
}
#define CP_COMMIT() asm volatile("cp.async.commit_group;" ::: "memory")
#define CP_WAIT1()  asm volatile("cp.async.wait_group 1;" ::: "memory")
#define CP_WAIT0()  asm volatile("cp.async.wait_group 0;" ::: "memory")

__device__ __forceinline__ void ldsm4(uint32_t* r, uint32_t addr) {
    asm volatile("ldmatrix.sync.aligned.m8n8.x4.shared.b16 {%0,%1,%2,%3}, [%4];"
        : "=r"(r[0]), "=r"(r[1]), "=r"(r[2]), "=r"(r[3]) : "r"(addr));
}
__device__ __forceinline__ void ldsm4t(uint32_t* r, uint32_t addr) {
    asm volatile("ldmatrix.sync.aligned.m8n8.x4.trans.shared.b16 {%0,%1,%2,%3}, [%4];"
        : "=r"(r[0]), "=r"(r[1]), "=r"(r[2]), "=r"(r[3]) : "r"(addr));
}
__device__ __forceinline__ void mma_f16(float* c, const uint32_t* a, uint32_t b0, uint32_t b1) {
    asm volatile(
        "mma.sync.aligned.m16n8k16.row.col.f32.f16.f16.f32 "
        "{%0,%1,%2,%3}, {%4,%5,%6,%7}, {%8,%9}, {%0,%1,%2,%3};"
        : "+f"(c[0]), "+f"(c[1]), "+f"(c[2]), "+f"(c[3])
        : "r"(a[0]), "r"(a[1]), "r"(a[2]), "r"(a[3]), "r"(b0), "r"(b1));
}
__device__ __forceinline__ uint32_t pack_f16(float x, float y) {
    __half2 t = __floats2half2_rn(x, y);
    return *(uint32_t*)&t;
}

// -------------------- mask dtype detection ------------------------------------
__global__ void detect_mask_kernel(const unsigned int* __restrict__ m) {
    __shared__ int s01, sf;
    if (threadIdx.x == 0) { s01 = 1; sf = 1; }
    __syncthreads();
    unsigned int v = m[threadIdx.x];
    if (v > 1u) s01 = 0;
    if (v != 0u && v != 0x3F800000u) sf = 0;
    __syncthreads();
    if (threadIdx.x == 0) g_mask_fmt = s01 ? 0 : (sf ? 1 : 2);
}

// -------------------- fused prep: tohalf + W^T convert + mask bit-pack ---------
// blocks [0, 8192)     : x -> fp16        blocks [8192, 12288): W -> W^T fp16
// blocks [12288, 28672): mask -> bit-pack
#define PREP_GRID 28672

__global__ void prep_kernel(
    const float* __restrict__ x, __half* __restrict__ xf,
    const float* __restrict__ W0, const float* __restrict__ W1,
    const float* __restrict__ W2, const float* __restrict__ W3,
    __half* __restrict__ wth,
    const void* __restrict__ m, unsigned long long* __restrict__ mout)
{
    __shared__ float t[32][33];
    const int b = blockIdx.x;
    const int tid = threadIdx.x;

    if (b < 8192) {
        int i = b * 256 + tid;
        float4 v = ((const float4*)x)[i];
        __half2* o2 = (__half2*)xf;
        o2[i * 2]     = __floats2half2_rn(v.x, v.y);
        o2[i * 2 + 1] = __floats2half2_rn(v.z, v.w);
    } else if (b < 12288) {
        int bb = b - 8192;
        int z = bb >> 10, rem = bb & 1023;
        int by = rem >> 5, bx = rem & 31;
        const float* W = (z == 0) ? W0 : (z == 1) ? W1 : (z == 2) ? W2 : W3;
        int tx = tid & 31, ty = tid >> 5;          // 32 x 8
        int k0 = by * 32, n0 = bx * 32;
#pragma unroll
        for (int j = 0; j < 4; j++)
            t[ty + 8 * j][tx] = W[(size_t)(k0 + ty + 8 * j) * EE + n0 + tx];
        __syncthreads();
        size_t off = (size_t)z << 20;
#pragma unroll
        for (int j = 0; j < 4; j++)
            wth[off + (size_t)(n0 + ty + 8 * j) * EE + k0 + tx] =
                __float2half(t[tx][ty + 8 * j]);
    } else {
        int gw = (b - 12288) * 8 + (tid >> 5);
        int lane = tid & 31;
        int n = gw >> 14;
        int rem = gw & 16383;
        int qrow = rem >> 4;
        int kt = rem & 15;
        size_t base = ((size_t)(n * SQ + qrow)) * SQ + kt * 64;
        int fmt = g_mask_fmt;
        unsigned a, bb;
        if (fmt == 2) {
            const unsigned char* p = (const unsigned char*)m + base;
            a = (p[lane] != 0); bb = (p[lane + 32] != 0);
        } else {
            const unsigned* p = (const unsigned*)m + base;
            unsigned va = p[lane], vb = p[lane + 32];
            if (fmt == 1) { va &= 0x7fffffffu; vb &= 0x7fffffffu; }
            a = (va != 0); bb = (vb != 0);
        }
        unsigned lo = __ballot_sync(0xffffffffu, a);
        unsigned hi = __ballot_sync(0xffffffffu, bb);
        if (lane == 0)
            mout[((size_t)(n * 16 + kt)) * SQ + qrow] =
                ((unsigned long long)hi << 32) | lo;
    }
}

// -------------------- single-product fp16 GEMM (KC=32, 2 CTAs/SM) --------------
#define TSZ        8192
#define STAGE_B    (2 * TSZ)      // 16KB
#define GEMM_SMEM  (3 * STAGE_B)  // 48KB
#define NKC        32

__device__ __forceinline__ void load_stage(
    uint32_t sb, const __half* af, const __half* bh, int kc, int tid)
{
    const __half* bases[2] = {af, bh};
#pragma unroll
    for (int t2 = 0; t2 < 2; t2++) {
        const __half* base = bases[t2] + kc * 32;
        uint32_t dtile = sb + t2 * TSZ;
#pragma unroll
        for (int p = 0; p < 2; p++) {
            int idx = p * 256 + tid;
            int r = idx >> 2, c = idx & 3;
            cp_async16(dtile + r * 64 + ((c ^ ((r >> 1) & 3)) << 4),
                       base + (size_t)r * EE + c * 8);
        }
    }
}

__global__ void __launch_bounds__(256, 2) gemm_mma_kernel(
    const __half* __restrict__ Af, const __half* __restrict__ Wh,
    const float* __restrict__ b0, const float* __restrict__ b1, const float* __restrict__ b2,
    float* fo, __half* f0, __half* f1, __half* f2,
    float s0, float s1, float s2,
    int headmajor, int wbase)
{
    extern __shared__ char smem[];
    const uint32_t sbase = smem_u32(smem);
    const int tid = threadIdx.x;
    const int z = blockIdx.z;
    const float* bias = (z == 0) ? b0 : (z == 1) ? b1 : b2;
    __half* hf = (z == 0) ? f0 : (z == 1) ? f1 : f2;
    const float osc = (z == 0) ? s0 : (z == 1) ? s1 : s2;
    const size_t woff = ((size_t)(wbase + z)) << 20;

    const int mBase = blockIdx.y * 128;
    const int nBase = blockIdx.x * 128;
    const __half* af = Af + (size_t)mBase * EE;
    const __half* bh = Wh + woff + (size_t)nBase * EE;

    load_stage(sbase + 0 * STAGE_B, af, bh, 0, tid);
    CP_COMMIT();
    load_stage(sbase + 1 * STAGE_B, af, bh, 1, tid);
    CP_COMMIT();

    const int lane = tid & 31;
    const int wm = (tid >> 5) & 1;
    const int wn = tid >> 6;
    const int l15 = lane & 15, l16 = lane >> 4;

    float c[4][4][4];
#pragma unroll
    for (int i = 0; i < 4; i++)
#pragma unroll
        for (int j = 0; j < 4; j++)
#pragma unroll
            for (int q = 0; q < 4; q++) c[i][j][q] = 0.0f;

    for (int kc = 0; kc < NKC; kc++) {
        CP_WAIT1();
        __syncthreads();
        if (kc + 2 < NKC)
            load_stage(sbase + ((kc + 2) % 3) * STAGE_B, af, bh, kc + 2, tid);
        CP_COMMIT();

        const uint32_t sb = sbase + (kc % 3) * STAGE_B;
#pragma unroll
        for (int ko = 0; ko < 2; ko++) {
            uint32_t a[4][4], bh0[4], bh1[4];
            const int ch = ko * 2 + l16;
#pragma unroll
            for (int i = 0; i < 4; i++) {
                int r = wm * 64 + i * 16 + l15;
                ldsm4(a[i], sb + r * 64 + ((ch ^ ((r >> 1) & 3)) << 4));
            }
            {
                int r0 = wn * 32 + l15;
                int r1 = wn * 32 + 16 + l15;
                ldsm4(bh0, sb + TSZ + r0 * 64 + ((ch ^ ((r0 >> 1) & 3)) << 4));
                ldsm4(bh1, sb + TSZ + r1 * 64 + ((ch ^ ((r1 >> 1) & 3)) << 4));
            }
#pragma unroll
            for (int i = 0; i < 4; i++) {
                mma_f16(c[i][0], a[i], bh0[0], bh0[2]);
                mma_f16(c[i][1], a[i], bh0[1], bh0[3]);
                mma_f16(c[i][2], a[i], bh1[0], bh1[2]);
                mma_f16(c[i][3], a[i], bh1[1], bh1[3]);
            }
        }
    }

    const int lr = lane >> 2, lc = lane & 3;
#pragma unroll
    for (int i = 0; i < 4; i++) {
#pragma unroll
        for (int half = 0; half < 2; half++) {
            const int R = mBase + wm * 64 + i * 16 + half * 8 + lr;
#pragma unroll
            for (int j = 0; j < 4; j++) {
                const int C0 = nBase + wn * 32 + j * 8 + lc * 2;
                float2 bv = *(const float2*)(bias + C0);
                float vx = (c[i][j][half * 2 + 0] + bv.x) * osc;
                float vy = (c[i][j][half * 2 + 1] + bv.y) * osc;
                if (headmajor) {
                    const int nidx = R >> 10, sidx = R & 1023;
                    const int head = C0 >> 6, dd = C0 & 63;
                    size_t off = (((size_t)(nidx * HH + head) * SQ + sidx) << 6) + dd;
                    *(__half2*)(hf + off) = __floats2half2_rn(vx, vy);
                } else {
                    *(float2*)(fo + (size_t)R * EE + C0) = make_float2(vx, vy);
                }
            }
        }
    }
}

// -------------------- flash attention, fp16 mma, ALU-lean ----------------------
// CTA: 128 q-rows x 1 head; 8 warps x 16 rows; kv tiles of 64.
// Q pre-scaled by SCL2 -> logits in log2 domain.
#define A_ST0    16384
#define A_STG    17408
#define A_V      8192
#define A_MB     16384
#define ATT_SMEM (A_ST0 + 2 * A_STG)

__global__ void __launch_bounds__(256, 2) attn_mma_kernel(
    const __half* __restrict__ Qf, const __half* __restrict__ Kf,
    const __half* __restrict__ Vf,
    const unsigned long long* __restrict__ maskb,
    __half* __restrict__ Of)
{
    extern __shared__ char smem[];
    const uint32_t sb = smem_u32(smem);
    const int tid = threadIdx.x;
    const int qt = blockIdx.x, h = blockIdx.y, n = blockIdx.z;

    const size_t hoff = (size_t)(n * HH + h) * SQ * DK;
    const __half* qf = Qf + hoff + (size_t)qt * 128 * DK;

    // per-thread load-lane geometry (loop-invariant)
    const int rA = tid >> 3,        cA = tid & 7;
    const int rB = (256 + tid) >> 3, cB = (256 + tid) & 7;
    const uint32_t swA = rA * 128 + ((cA ^ (rA & 7)) << 4);
    const uint32_t swB = rB * 128 + ((cB ^ (rB & 7)) << 4);
    const uint32_t stg0 = sb + A_ST0, stg1 = sb + A_ST0 + A_STG;

    // loop-carried source pointers (advance 4096 halfs = one 64x64 tile per kt)
    const __half* kP0 = Kf + hoff + rA * 64 + cA * 8;
    const __half* kP1 = Kf + hoff + rB * 64 + cB * 8;
    const __half* vP0 = Vf + hoff + rA * 64 + cA * 8;
    const __half* vP1 = Vf + hoff + rB * 64 + cB * 8;
    const unsigned long long* mP =
        maskb + (size_t)n * 16 * SQ + qt * 128 + tid * 2;   // valid for tid<64

    // Q load (one-time) + kv tile 0
#pragma unroll
    for (int p = 0; p < 4; p++) {
        int idx = p * 256 + tid;
        int r = idx >> 3, c = idx & 7;
        cp_async16(sb + r * 128 + ((c ^ (r & 7)) << 4), qf + r * 64 + c * 8);
    }
    cp_async16(stg0 + swA, kP0);
    cp_async16(stg0 + swB, kP1);
    cp_async16(stg0 + A_V + swA, vP0);
    cp_async16(stg0 + A_V + swB, vP1);
    if (tid < 64) cp_async16(stg0 + A_MB + tid * 16, mP);
    CP_COMMIT();
    kP0 += 4096; kP1 += 4096; vP0 += 4096; vP1 += 4096; mP += SQ;

    const int w = tid >> 5, lane = tid & 31;
    const int l15 = lane & 15, l16 = lane >> 4;
    const int lr = lane >> 2, lc = lane & 3;
    const int row0 = w * 16 + lr;
    const int qg0 = qt * 128 + row0;
    const int qg1 = qg0 + 8;
    const int xw = l15 & 7;   // swizzle XOR term: rk&7 == l15&7 for all mma rows

    // loop-invariant ldsm offsets (relative to stage base)
    uint32_t koff[4], voff[4];
#pragma unroll
    for (int ko = 0; ko < 4; ko++)
        koff[ko] = l15 * 128 + (((2 * ko + l16) ^ xw) << 4);
#pragma unroll
    for (int dt2 = 0; dt2 < 4; dt2++)
        voff[dt2] = A_V + l15 * 128 + (((2 * dt2 + l16) ^ xw) << 4);

    CP_WAIT0();
    __syncthreads();

    // hoist Q fragments for the whole loop
    uint32_t aq[4][4];
#pragma unroll
    for (int ko = 0; ko < 4; ko++)
        ldsm4(aq[ko], sb + w * 16 * 128 + koff[ko] - l15 * 128 + l15 * 128 + (w * 16) * 0);
    // (rewritten cleanly below; keep canonical form)
#pragma unroll
    for (int ko = 0; ko < 4; ko++) {
        int r = w * 16 + l15;
        int ch = 2 * ko + l16;
        ldsm4(aq[ko], sb + r * 128 + ((ch ^ (r & 7)) << 4));
    }

    float o[8][4];
#pragma unroll
    for (int i = 0; i < 8; i++)
#pragma unroll
        for (int j = 0; j < 4; j++) o[i][j] = 0.0f;
    float m0 = -1e30f, m1 = -1e30f, l0 = 0.0f, l1 = 0.0f;

    for (int kt = 0; kt < 16; kt++) {
        // prefetch kt+1 into the other buffer
        if (kt + 1 < 16) {
            const uint32_t dt = ((kt + 1) & 1) ? stg1 : stg0;
            cp_async16(dt + swA, kP0);
            cp_async16(dt + swB, kP1);
            cp_async16(dt + A_V + swA, vP0);
            cp_async16(dt + A_V + swB, vP1);
            if (tid < 64) cp_async16(dt + A_MB + tid * 16, mP);
            kP0 += 4096; kP1 += 4096; vP0 += 4096; vP1 += 4096; mP += SQ;
        }
        CP_COMMIT();

        const uint32_t stg = (kt & 1) ? stg1 : stg0;
        const char* msp = smem + (A_ST0 + (kt & 1) * A_STG + A_MB);

        // ---- S = Q K^T ----
        float s[8][4];
#pragma unroll
        for (int i = 0; i < 8; i++)
#pragma unroll
            for (int j = 0; j < 4; j++) s[i][j] = 0.0f;

#pragma unroll
        for (int ko = 0; ko < 4; ko++) {
#pragma unroll
            for (int nt2 = 0; nt2 < 4; nt2++) {
                uint32_t kb[4];
                ldsm4(kb, stg + koff[ko] + nt2 * 2048);
                mma_f16(s[2 * nt2],     aq[ko], kb[0], kb[2]);
                mma_f16(s[2 * nt2 + 1], aq[ko], kb[1], kb[3]);
            }
        }

        // ---- mask: preshifted words + constant-bit tests ----
        unsigned long long mq0 = *(const unsigned long long*)(msp + row0 * 8) >> (2 * lc);
        unsigned long long mq1 = *(const unsigned long long*)(msp + (row0 + 8) * 8) >> (2 * lc);
#pragma unroll
        for (int nt = 0; nt < 8; nt++) {
            if (mq0 & (1ULL << (nt * 8)))       s[nt][0] = -1e9f;
            if (mq0 & (2ULL << (nt * 8)))       s[nt][1] = -1e9f;
            if (mq1 & (1ULL << (nt * 8)))       s[nt][2] = -1e9f;
            if (mq1 & (2ULL << (nt * 8)))       s[nt][3] = -1e9f;
        }

        // ---- online softmax (base-2) ----
        float vx0 = -1e30f, vx1 = -1e30f;
#pragma unroll
        for (int nt = 0; nt < 8; nt++) {
            vx0 = fmaxf(vx0, fmaxf(s[nt][0], s[nt][1]));
            vx1 = fmaxf(vx1, fmaxf(s[nt][2], s[nt][3]));
        }
        vx0 = fmaxf(vx0, __shfl_xor_sync(0xffffffffu, vx0, 1));
        vx0 = fmaxf(vx0, __shfl_xor_sync(0xffffffffu, vx0, 2));
        vx1 = fmaxf(vx1, __shfl_xor_sync(0xffffffffu, vx1, 1));
        vx1 = fmaxf(vx1, __shfl_xor_sync(0xffffffffu, vx1, 2));

        const float mn0 = fmaxf(m0, vx0), mn1 = fmaxf(m1, vx1);
        const float a0 = exp2f(m0 - mn0), a1 = exp2f(m1 - mn1);
        m0 = mn0; m1 = mn1;
        float sum0 = 0.0f, sum1 = 0.0f;
#pragma unroll
        for (int nt = 0; nt < 8; nt++) {
            s[nt][0] = exp2f(s[nt][0] - mn0);
            s[nt][1] = exp2f(s[nt][1] - mn0);
            s[nt][2] = exp2f(s[nt][2] - mn1);
            s[nt][3] = exp2f(s[nt][3] - mn1);
            sum0 += s[nt][0] + s[nt][1];
            sum1 += s[nt][2] + s[nt][3];
        }
        sum0 += __shfl_xor_sync(0xffffffffu, sum0, 1);
        sum0 += __shfl_xor_sync(0xffffffffu, sum0, 2);
        sum1 += __shfl_xor_sync(0xffffffffu, sum1, 1);
        sum1 += __shfl_xor_sync(0xffffffffu, sum1, 2);
        l0 = l0 * a0 + sum0;
        l1 = l1 * a1 + sum1;
#pragma unroll
        for (int nt = 0; nt < 8; nt++) {
            o[nt][0] *= a0; o[nt][1] *= a0;
            o[nt][2] *= a1; o[nt][3] *= a1;
        }

        // ---- O += P V ----
#pragma unroll
        for (int t = 0; t < 4; t++) {
            uint32_t ph[4];
            ph[0] = pack_f16(s[2 * t][0],     s[2 * t][1]);
            ph[1] = pack_f16(s[2 * t][2],     s[2 * t][3]);
            ph[2] = pack_f16(s[2 * t + 1][0], s[2 * t + 1][1]);
            ph[3] = pack_f16(s[2 * t + 1][2], s[2 * t + 1][3]);
#pragma unroll
            for (int dt2 = 0; dt2 < 4; dt2++) {
                uint32_t vb[4];
                ldsm4t(vb, stg + voff[dt2] + t * 2048);
                mma_f16(o[2 * dt2],     ph, vb[0], vb[1]);
                mma_f16(o[2 * dt2 + 1], ph, vb[2], vb[3]);
            }
        }

        if (kt + 1 < 16) {
            CP_WAIT0();       // drain prefetch for kt+1
            __syncthreads();  // all warps done with current buffer
        }
    }

    // ---- epilogue: normalize, store fp16 [n,s,e] ----
    const float inv0 = 1.0f / l0, inv1 = 1.0f / l1;
    const size_t base0 = ((size_t)n * SQ + qg0) * EE + h * DK + 2 * lc;
    const size_t base1 = ((size_t)n * SQ + qg1) * EE + h * DK + 2 * lc;
#pragma unroll
    for (int nt = 0; nt < 8; nt++) {
        *(__half2*)(Of + base0 + nt * 8) =
            __floats2half2_rn(o[nt][0] * inv0, o[nt][1] * inv0);
        *(__half2*)(Of + base1 + nt * 8) =
            __floats2half2_rn(o[nt][2] * inv1, o[nt][3] * inv1);
    }
}

// -------------------- launch ---------------------------------------------------
extern "C" void kernel_launch(void* const* d_in, const int* in_sizes, int n_in,
                              void* d_out, int out_size)
{
    const float* x    = (const float*)d_in[0];
    const void*  mask = d_in[1];
    const float* Wq   = (const float*)d_in[2];
    const float* bq   = (const float*)d_in[3];
    const float* Wk   = (const float*)d_in[4];
    const float* bk   = (const float*)d_in[5];
    const float* Wv   = (const float*)d_in[6];
    const float* bv   = (const float*)d_in[7];
    const float* Wo   = (const float*)d_in[8];
    const float* bo   = (const float*)d_in[9];
    float* out = (float*)d_out;

    unsigned long long* mb;
    cudaGetSymbolAddress((void**)&mb, g_maskb);
    __half *xf, *wth, *qf, *kf, *vf, *aof;
    cudaGetSymbolAddress((void**)&xf,  g_xf);
    cudaGetSymbolAddress((void**)&wth, g_wth);
    cudaGetSymbolAddress((void**)&qf,  g_qf);
    cudaGetSymbolAddress((void**)&kf,  g_kf);
    cudaGetSymbolAddress((void**)&vf,  g_vf);
    cudaGetSymbolAddress((void**)&aof, g_aof);

    cudaFuncSetAttribute(gemm_mma_kernel,
                         cudaFuncAttributeMaxDynamicSharedMemorySize, GEMM_SMEM);
    cudaFuncSetAttribute(attn_mma_kernel,
                         cudaFuncAttributeMaxDynamicSharedMemorySize, ATT_SMEM);

    // 1. mask dtype detect
    detect_mask_kernel<<<1, 256>>>((const unsigned int*)mask);

    // 2. fused prep: x->fp16, W->W^T fp16, mask->bits
    prep_kernel<<<PREP_GRID, 256>>>(x, xf, Wq, Wk, Wv, Wo, wth, mask, mb);

    // 3. QKV projections -> fp16 head-major (Q pre-scaled by SCL2)
    gemm_mma_kernel<<<dim3(EE / 128, NB * SQ / 128, 3), 256, GEMM_SMEM>>>(
        xf, wth, bq, bk, bv, nullptr, qf, kf, vf,
        SCL2, 1.0f, 1.0f, 1, 0);

    // 4. flash attention (fp16 tensor cores) -> fp16 [n,s,e]
    attn_mma_kernel<<<dim3(SQ / 128, HH, NB), 256, ATT_SMEM>>>(
        qf, kf, vf, mb, aof);

    // 5. out projection -> f32 out
    gemm_mma_kernel<<<dim3(EE / 128, NB * SQ / 128, 1), 256, GEMM_SMEM>>>(
        aof, wth, bo, bo, bo, out,
        nullptr, nullptr, nullptr, 1.0f, 1.0f, 1.0f, 0, 3);
}

// round 16
// speedup vs baseline: 1.0945x; 1.0001x over previous
#include <cuda_runtime.h>
#include <cuda_bf16.h>
#include <cuda_fp16.h>
#include <cstdint>

// Problem dims
#define NB   8
#define SQ   1024
#define EE   1024
#define HH   16
#define DK   64

// -------------------- scratch (static device arrays; no allocation) -----------
__device__ unsigned long long g_maskb[NB * SQ * 16];   // bit-packed, [n][kt][qrow]
__device__ int g_mask_fmt;

__device__ __half g_xf[NB * SQ * EE];            // x fp16
__device__ __half g_wth[4 * EE * EE];            // W^T fp16, [n][k], 4 mats
__device__ __half g_qf[NB * HH * SQ * DK];       // [n,h,s,d] fp16 (pre-scaled by SCL2)
__device__ __half g_kf[NB * HH * SQ * DK];
__device__ __half g_vf[NB * HH * SQ * DK];
__device__ __half g_aof[NB * SQ * EE];           // attn-out fp16, [n,s,e]

#define SCL2 0.1803368801111244f   // 0.125 * log2(e)

// -------------------- helpers --------------------------------------------------
__device__ __forceinline__ uint32_t smem_u32(const void* p) {
    uint32_t a;
    asm("{ .reg .u64 t; cvta.to.shared.u64 t, %1; cvt.u32.u64 %0, t; }" : "=r"(a) : "l"(p));
    return a;
}
__device__ __forceinline__ void cp_async16(uint32_t dst, const void* src) {
    asm volatile("cp.async.cg.shared.global [%0], [%1], 16;" :: "r"(dst), "l"(src));
}
#define CP_COMMIT() asm volatile("cp.async.commit_group;" ::: "memory")
#define CP_WAIT1()  asm volatile("cp.async.wait_group 1;" ::: "memory")
#define CP_WAIT0()  asm volatile("cp.async.wait_group 0;" ::: "memory")

__device__ __forceinline__ void ldsm4(uint32_t* r, uint32_t addr) {
    asm volatile("ldmatrix.sync.aligned.m8n8.x4.shared.b16 {%0,%1,%2,%3}, [%4];"
        : "=r"(r[0]), "=r"(r[1]), "=r"(r[2]), "=r"(r[3]) : "r"(addr));
}
__device__ __forceinline__ void ldsm4t(uint32_t* r, uint32_t addr) {
    asm volatile("ldmatrix.sync.aligned.m8n8.x4.trans.shared.b16 {%0,%1,%2,%3}, [%4];"
        : "=r"(r[0]), "=r"(r[1]), "=r"(r[2]), "=r"(r[3]) : "r"(addr));
}
__device__ __forceinline__ void mma_f16(float* c, const uint32_t* a, uint32_t b0, uint32_t b1) {
    asm volatile(
        "mma.sync.aligned.m16n8k16.row.col.f32.f16.f16.f32 "
        "{%0,%1,%2,%3}, {%4,%5,%6,%7}, {%8,%9}, {%0,%1,%2,%3};"
        : "+f"(c[0]), "+f"(c[1]), "+f"(c[2]), "+f"(c[3])
        : "r"(a[0]), "r"(a[1]), "r"(a[2]), "r"(a[3]), "r"(b0), "r"(b1));
}
__device__ __forceinline__ uint32_t pack_f16(float x, float y) {
    __half2 t = __floats2half2_rn(x, y);
    return *(uint32_t*)&t;
}

// -------------------- mask dtype detection ------------------------------------
__global__ void detect_mask_kernel(const unsigned int* __restrict__ m) {
    __shared__ int s01, sf;
    if (threadIdx.x == 0) { s01 = 1; sf = 1; }
    __syncthreads();
    unsigned int v = m[threadIdx.x];
    if (v > 1u) s01 = 0;
    if (v != 0u && v != 0x3F800000u) sf = 0;
    __syncthreads();
    if (threadIdx.x == 0) g_mask_fmt = s01 ? 0 : (sf ? 1 : 2);
}

// -------------------- fused prep: tohalf + W^T convert + mask bit-pack ---------
#define PREP_GRID 28672

__global__ void prep_kernel(
    const float* __restrict__ x, __half* __restrict__ xf,
    const float* __restrict__ W0, const float* __restrict__ W1,
    const float* __restrict__ W2, const float* __restrict__ W3,
    __half* __restrict__ wth,
    const void* __restrict__ m, unsigned long long* __restrict__ mout)
{
    __shared__ float t[32][33];
    const int b = blockIdx.x;
    const int tid = threadIdx.x;

    if (b < 8192) {
        int i = b * 256 + tid;
        float4 v = ((const float4*)x)[i];
        __half2* o2 = (__half2*)xf;
        o2[i * 2]     = __floats2half2_rn(v.x, v.y);
        o2[i * 2 + 1] = __floats2half2_rn(v.z, v.w);
    } else if (b < 12288) {
        int bb = b - 8192;
        int z = bb >> 10, rem = bb & 1023;
        int by = rem >> 5, bx = rem & 31;
        const float* W = (z == 0) ? W0 : (z == 1) ? W1 : (z == 2) ? W2 : W3;
        int tx = tid & 31, ty = tid >> 5;
        int k0 = by * 32, n0 = bx * 32;
#pragma unroll
        for (int j = 0; j < 4; j++)
            t[ty + 8 * j][tx] = W[(size_t)(k0 + ty + 8 * j) * EE + n0 + tx];
        __syncthreads();
        size_t off = (size_t)z << 20;
#pragma unroll
        for (int j = 0; j < 4; j++)
            wth[off + (size_t)(n0 + ty + 8 * j) * EE + k0 + tx] =
                __float2half(t[tx][ty + 8 * j]);
    } else {
        int gw = (b - 12288) * 8 + (tid >> 5);
        int lane = tid & 31;
        int n = gw >> 14;
        int rem = gw & 16383;
        int qrow = rem >> 4;
        int kt = rem & 15;
        size_t base = ((size_t)(n * SQ + qrow)) * SQ + kt * 64;
        int fmt = g_mask_fmt;
        unsigned a, bb;
        if (fmt == 2) {
            const unsigned char* p = (const unsigned char*)m + base;
            a = (p[lane] != 0); bb = (p[lane + 32] != 0);
        } else {
            const unsigned* p = (const unsigned*)m + base;
            unsigned va = p[lane], vb = p[lane + 32];
            if (fmt == 1) { va &= 0x7fffffffu; vb &= 0x7fffffffu; }
            a = (va != 0); bb = (vb != 0);
        }
        unsigned lo = __ballot_sync(0xffffffffu, a);
        unsigned hi = __ballot_sync(0xffffffffu, bb);
        if (lane == 0)
            mout[((size_t)(n * 16 + kt)) * SQ + qrow] =
                ((unsigned long long)hi << 32) | lo;
    }
}

// -------------------- single-product fp16 GEMM (KC=32, 2 CTAs/SM) --------------
#define TSZ        8192
#define STAGE_B    (2 * TSZ)      // 16KB
#define GEMM_SMEM  (3 * STAGE_B)  // 48KB
#define NKC        32

__device__ __forceinline__ void load_stage(
    uint32_t sb, const __half* af, const __half* bh, int kc, int tid)
{
    const __half* bases[2] = {af, bh};
#pragma unroll
    for (int t2 = 0; t2 < 2; t2++) {
        const __half* base = bases[t2] + kc * 32;
        uint32_t dtile = sb + t2 * TSZ;
#pragma unroll
        for (int p = 0; p < 2; p++) {
            int idx = p * 256 + tid;
            int r = idx >> 2, c = idx & 3;
            cp_async16(dtile + r * 64 + ((c ^ ((r >> 1) & 3)) << 4),
                       base + (size_t)r * EE + c * 8);
        }
    }
}

__global__ void __launch_bounds__(256, 2) gemm_mma_kernel(
    const __half* __restrict__ Af, const __half* __restrict__ Wh,
    const float* __restrict__ b0, const float* __restrict__ b1, const float* __restrict__ b2,
    float* fo, __half* f0, __half* f1, __half* f2,
    float s0, float s1, float s2,
    int headmajor, int wbase)
{
    extern __shared__ char smem[];
    const uint32_t sbase = smem_u32(smem);
    const int tid = threadIdx.x;
    const int z = blockIdx.z;
    const float* bias = (z == 0) ? b0 : (z == 1) ? b1 : b2;
    __half* hf = (z == 0) ? f0 : (z == 1) ? f1 : f2;
    const float osc = (z == 0) ? s0 : (z == 1) ? s1 : s2;
    const size_t woff = ((size_t)(wbase + z)) << 20;

    const int mBase = blockIdx.y * 128;
    const int nBase = blockIdx.x * 128;
    const __half* af = Af + (size_t)mBase * EE;
    const __half* bh = Wh + woff + (size_t)nBase * EE;

    load_stage(sbase + 0 * STAGE_B, af, bh, 0, tid);
    CP_COMMIT();
    load_stage(sbase + 1 * STAGE_B, af, bh, 1, tid);
    CP_COMMIT();

    const int lane = tid & 31;
    const int wm = (tid >> 5) & 1;
    const int wn = tid >> 6;
    const int l15 = lane & 15, l16 = lane >> 4;

    float c[4][4][4];
#pragma unroll
    for (int i = 0; i < 4; i++)
#pragma unroll
        for (int j = 0; j < 4; j++)
#pragma unroll
            for (int q = 0; q < 4; q++) c[i][j][q] = 0.0f;

    for (int kc = 0; kc < NKC; kc++) {
        CP_WAIT1();
        __syncthreads();
        if (kc + 2 < NKC)
            load_stage(sbase + ((kc + 2) % 3) * STAGE_B, af, bh, kc + 2, tid);
        CP_COMMIT();

        const uint32_t sb = sbase + (kc % 3) * STAGE_B;
#pragma unroll
        for (int ko = 0; ko < 2; ko++) {
            uint32_t a[4][4], bh0[4], bh1[4];
            const int ch = ko * 2 + l16;
#pragma unroll
            for (int i = 0; i < 4; i++) {
                int r = wm * 64 + i * 16 + l15;
                ldsm4(a[i], sb + r * 64 + ((ch ^ ((r >> 1) & 3)) << 4));
            }
            {
                int r0 = wn * 32 + l15;
                int r1 = wn * 32 + 16 + l15;
                ldsm4(bh0, sb + TSZ + r0 * 64 + ((ch ^ ((r0 >> 1) & 3)) << 4));
                ldsm4(bh1, sb + TSZ + r1 * 64 + ((ch ^ ((r1 >> 1) & 3)) << 4));
            }
#pragma unroll
            for (int i = 0; i < 4; i++) {
                mma_f16(c[i][0], a[i], bh0[0], bh0[2]);
                mma_f16(c[i][1], a[i], bh0[1], bh0[3]);
                mma_f16(c[i][2], a[i], bh1[0], bh1[2]);
                mma_f16(c[i][3], a[i], bh1[1], bh1[3]);
            }
        }
    }

    const int lr = lane >> 2, lc = lane & 3;
#pragma unroll
    for (int i = 0; i < 4; i++) {
#pragma unroll
        for (int half = 0; half < 2; half++) {
            const int R = mBase + wm * 64 + i * 16 + half * 8 + lr;
#pragma unroll
            for (int j = 0; j < 4; j++) {
                const int C0 = nBase + wn * 32 + j * 8 + lc * 2;
                float2 bv = *(const float2*)(bias + C0);
                float vx = (c[i][j][half * 2 + 0] + bv.x) * osc;
                float vy = (c[i][j][half * 2 + 1] + bv.y) * osc;
                if (headmajor) {
                    const int nidx = R >> 10, sidx = R & 1023;
                    const int head = C0 >> 6, dd = C0 & 63;
                    size_t off = (((size_t)(nidx * HH + head) * SQ + sidx) << 6) + dd;
                    *(__half2*)(hf + off) = __floats2half2_rn(vx, vy);
                } else {
                    *(float2*)(fo + (size_t)R * EE + C0) = make_float2(vx, vy);
                }
            }
        }
    }
}

// -------------------- flash attention, fp16 mma, ALU-lean ----------------------
#define A_ST0    16384
#define A_STG    17408
#define A_V      8192
#define A_MB     16384
#define ATT_SMEM (A_ST0 + 2 * A_STG)

__global__ void __launch_bounds__(256, 2) attn_mma_kernel(
    const __half* __restrict__ Qf, const __half* __restrict__ Kf,
    const __half* __restrict__ Vf,
    const unsigned long long* __restrict__ maskb,
    __half* __restrict__ Of)
{
    extern __shared__ char smem[];
    const uint32_t sb = smem_u32(smem);
    const int tid = threadIdx.x;
    const int qt = blockIdx.x, h = blockIdx.y, n = blockIdx.z;

    const size_t hoff = (size_t)(n * HH + h) * SQ * DK;
    const __half* qf = Qf + hoff + (size_t)qt * 128 * DK;

    // per-thread load-lane geometry (loop-invariant)
    const int rA = tid >> 3,         cA = tid & 7;
    const int rB = (256 + tid) >> 3, cB = (256 + tid) & 7;
    const uint32_t swA = rA * 128 + ((cA ^ (rA & 7)) << 4);
    const uint32_t swB = rB * 128 + ((cB ^ (rB & 7)) << 4);
    const uint32_t stg0 = sb + A_ST0, stg1 = sb + A_ST0 + A_STG;

    // loop-carried source pointers (advance one 64x64 tile per kt)
    const __half* kP0 = Kf + hoff + rA * 64 + cA * 8;
    const __half* kP1 = Kf + hoff + rB * 64 + cB * 8;
    const __half* vP0 = Vf + hoff + rA * 64 + cA * 8;
    const __half* vP1 = Vf + hoff + rB * 64 + cB * 8;
    const unsigned long long* mP =
        maskb + (size_t)n * 16 * SQ + qt * 128 + tid * 2;   // valid for tid<64

    // Q load (one-time) + kv tile 0
#pragma unroll
    for (int p = 0; p < 4; p++) {
        int idx = p * 256 + tid;
        int r = idx >> 3, c = idx & 7;
        cp_async16(sb + r * 128 + ((c ^ (r & 7)) << 4), qf + r * 64 + c * 8);
    }
    cp_async16(stg0 + swA, kP0);
    cp_async16(stg0 + swB, kP1);
    cp_async16(stg0 + A_V + swA, vP0);
    cp_async16(stg0 + A_V + swB, vP1);
    if (tid < 64) cp_async16(stg0 + A_MB + tid * 16, mP);
    CP_COMMIT();
    kP0 += 4096; kP1 += 4096; vP0 += 4096; vP1 += 4096; mP += SQ;

    const int w = tid >> 5, lane = tid & 31;
    const int l15 = lane & 15, l16 = lane >> 4;
    const int lr = lane >> 2, lc = lane & 3;
    const int row0 = w * 16 + lr;
    const int qg0 = qt * 128 + row0;
    const int qg1 = qg0 + 8;
    const int xw = l15 & 7;   // rk&7 == l15&7 for all mma rows

    // loop-invariant ldsm offsets (relative to stage base)
    uint32_t koff[4], voff[4];
#pragma unroll
    for (int ko = 0; ko < 4; ko++)
        koff[ko] = l15 * 128 + (((2 * ko + l16) ^ xw) << 4);
#pragma unroll
    for (int dt2 = 0; dt2 < 4; dt2++)
        voff[dt2] = A_V + l15 * 128 + (((2 * dt2 + l16) ^ xw) << 4);

    CP_WAIT0();
    __syncthreads();

    // hoist Q fragments for the whole loop
    uint32_t aq[4][4];
#pragma unroll
    for (int ko = 0; ko < 4; ko++) {
        int r = w * 16 + l15;
        int ch = 2 * ko + l16;
        ldsm4(aq[ko], sb + r * 128 + ((ch ^ (r & 7)) << 4));
    }

    float o[8][4];
#pragma unroll
    for (int i = 0; i < 8; i++)
#pragma unroll
        for (int j = 0; j < 4; j++) o[i][j] = 0.0f;
    float m0 = -1e30f, m1 = -1e30f, l0 = 0.0f, l1 = 0.0f;

    for (int kt = 0; kt < 16; kt++) {
        // prefetch kt+1 into the other buffer
        if (kt + 1 < 16) {
            const uint32_t dt = ((kt + 1) & 1) ? stg1 : stg0;
            cp_async16(dt + swA, kP0);
            cp_async16(dt + swB, kP1);
            cp_async16(dt + A_V + swA, vP0);
            cp_async16(dt + A_V + swB, vP1);
            if (tid < 64) cp_async16(dt + A_MB + tid * 16, mP);
            kP0 += 4096; kP1 += 4096; vP0 += 4096; vP1 += 4096; mP += SQ;
        }
        CP_COMMIT();

        const uint32_t stg = (kt & 1) ? stg1 : stg0;
        const char* msp = smem + (A_ST0 + (kt & 1) * A_STG + A_MB);

        // ---- S = Q K^T ----
        float s[8][4];
#pragma unroll
        for (int i = 0; i < 8; i++)
#pragma unroll
            for (int j = 0; j < 4; j++) s[i][j] = 0.0f;

#pragma unroll
        for (int ko = 0; ko < 4; ko++) {
#pragma unroll
            for (int nt2 = 0; nt2 < 4; nt2++) {
                uint32_t kb[4];
                ldsm4(kb, stg + koff[ko] + nt2 * 2048);
                mma_f16(s[2 * nt2],     aq[ko], kb[0], kb[2]);
                mma_f16(s[2 * nt2 + 1], aq[ko], kb[1], kb[3]);
            }
        }

        // ---- mask: preshifted 32-bit halves, constant-bit tests ----
        unsigned long long mq0 = *(const unsigned long long*)(msp + row0 * 8) >> (2 * lc);
        unsigned long long mq1 = *(const unsigned long long*)(msp + (row0 + 8) * 8) >> (2 * lc);
        const uint32_t a0lo = (uint32_t)mq0, a0hi = (uint32_t)(mq0 >> 32);
        const uint32_t a1lo = (uint32_t)mq1, a1hi = (uint32_t)(mq1 >> 32);
#pragma unroll
        for (int nt = 0; nt < 4; nt++) {
            const uint32_t b0 = 1u << (nt * 8), b1 = 2u << (nt * 8);
            if (a0lo & b0) s[nt][0] = -1e9f;
            if (a0lo & b1) s[nt][1] = -1e9f;
            if (a1lo & b0) s[nt][2] = -1e9f;
            if (a1lo & b1) s[nt][3] = -1e9f;
            if (a0hi & b0) s[nt + 4][0] = -1e9f;
            if (a0hi & b1) s[nt + 4][1] = -1e9f;
            if (a1hi & b0) s[nt + 4][2] = -1e9f;
            if (a1hi & b1) s[nt + 4][3] = -1e9f;
        }

        // ---- online softmax (base-2): max tree -> rescale o -> exp ----
        float vx0 = -1e30f, vx1 = -1e30f;
#pragma unroll
        for (int nt = 0; nt < 8; nt++) {
            vx0 = fmaxf(vx0, fmaxf(s[nt][0], s[nt][1]));
            vx1 = fmaxf(vx1, fmaxf(s[nt][2], s[nt][3]));
        }
        vx0 = fmaxf(vx0, __shfl_xor_sync(0xffffffffu, vx0, 1));
        vx0 = fmaxf(vx0, __shfl_xor_sync(0xffffffffu, vx0, 2));
        vx1 = fmaxf(vx1, __shfl_xor_sync(0xffffffffu, vx1, 1));
        vx1 = fmaxf(vx1, __shfl_xor_sync(0xffffffffu, vx1, 2));

        const float mn0 = fmaxf(m0, vx0), mn1 = fmaxf(m1, vx1);
        const float a0 = exp2f(m0 - mn0), a1 = exp2f(m1 - mn1);
        m0 = mn0; m1 = mn1;
#pragma unroll
        for (int nt = 0; nt < 8; nt++) {
            o[nt][0] *= a0; o[nt][1] *= a0;
            o[nt][2] *= a1; o[nt][3] *= a1;
        }

        float sum0 = 0.0f, sum1 = 0.0f;
#pragma unroll
        for (int nt = 0; nt < 8; nt++) {
            s[nt][0] = exp2f(s[nt][0] - mn0);
            s[nt][1] = exp2f(s[nt][1] - mn0);
            s[nt][2] = exp2f(s[nt][2] - mn1);
            s[nt][3] = exp2f(s[nt][3] - mn1);
            sum0 += s[nt][0] + s[nt][1];
            sum1 += s[nt][2] + s[nt][3];
        }

        // ---- O += P V (issue tensor work before the sum shfls) ----
#pragma unroll
        for (int t = 0; t < 4; t++) {
            uint32_t ph[4];
            ph[0] = pack_f16(s[2 * t][0],     s[2 * t][1]);
            ph[1] = pack_f16(s[2 * t][2],     s[2 * t][3]);
            ph[2] = pack_f16(s[2 * t + 1][0], s[2 * t + 1][1]);
            ph[3] = pack_f16(s[2 * t + 1][2], s[2 * t + 1][3]);
#pragma unroll
            for (int dt2 = 0; dt2 < 4; dt2++) {
                uint32_t vb[4];
                ldsm4t(vb, stg + voff[dt2] + t * 2048);
                mma_f16(o[2 * dt2],     ph, vb[0], vb[1]);
                mma_f16(o[2 * dt2 + 1], ph, vb[2], vb[3]);
            }
        }

        // ---- deferred sum reduction + l update ----
        sum0 += __shfl_xor_sync(0xffffffffu, sum0, 1);
        sum0 += __shfl_xor_sync(0xffffffffu, sum0, 2);
        sum1 += __shfl_xor_sync(0xffffffffu, sum1, 1);
        sum1 += __shfl_xor_sync(0xffffffffu, sum1, 2);
        l0 = l0 * a0 + sum0;
        l1 = l1 * a1 + sum1;

        if (kt + 1 < 16) {
            CP_WAIT0();       // drain prefetch for kt+1
            __syncthreads();  // all warps done with current buffer
        }
    }

    // ---- epilogue: normalize, store fp16 [n,s,e] ----
    const float inv0 = 1.0f / l0, inv1 = 1.0f / l1;
    const size_t base0 = ((size_t)n * SQ + qg0) * EE + h * DK + 2 * lc;
    const size_t base1 = ((size_t)n * SQ + qg1) * EE + h * DK + 2 * lc;
#pragma unroll
    for (int nt = 0; nt < 8; nt++) {
        *(__half2*)(Of + base0 + nt * 8) =
            __floats2half2_rn(o[nt][0] * inv0, o[nt][1] * inv0);
        *(__half2*)(Of + base1 + nt * 8) =
            __floats2half2_rn(o[nt][2] * inv1, o[nt][3] * inv1);
    }
}

// -------------------- launch ---------------------------------------------------
extern "C" void kernel_launch(void* const* d_in, const int* in_sizes, int n_in,
                              void* d_out, int out_size)
{
    const float* x    = (const float*)d_in[0];
    const void*  mask = d_in[1];
    const float* Wq   = (const float*)d_in[2];
    const float* bq   = (const float*)d_in[3];
    const float* Wk   = (const float*)d_in[4];
    const float* bk   = (const float*)d_in[5];
    const float* Wv   = (const float*)d_in[6];
    const float* bv   = (const float*)d_in[7];
    const float* Wo   = (const float*)d_in[8];
    const float* bo   = (const float*)d_in[9];
    float* out = (float*)d_out;

    unsigned long long* mb;
    cudaGetSymbolAddress((void**)&mb, g_maskb);
    __half *xf, *wth, *qf, *kf, *vf, *aof;
    cudaGetSymbolAddress((void**)&xf,  g_xf);
    cudaGetSymbolAddress((void**)&wth, g_wth);
    cudaGetSymbolAddress((void**)&qf,  g_qf);
    cudaGetSymbolAddress((void**)&kf,  g_kf);
    cudaGetSymbolAddress((void**)&vf,  g_vf);
    cudaGetSymbolAddress((void**)&aof, g_aof);

    cudaFuncSetAttribute(gemm_mma_kernel,
                         cudaFuncAttributeMaxDynamicSharedMemorySize, GEMM_SMEM);
    cudaFuncSetAttribute(attn_mma_kernel,
                         cudaFuncAttributeMaxDynamicSharedMemorySize, ATT_SMEM);

    // 1. mask dtype detect
    detect_mask_kernel<<<1, 256>>>((const unsigned int*)mask);

    // 2. fused prep: x->fp16, W->W^T fp16, mask->bits
    prep_kernel<<<PREP_GRID, 256>>>(x, xf, Wq, Wk, Wv, Wo, wth, mask, mb);

    // 3. QKV projections -> fp16 head-major (Q pre-scaled by SCL2)
    gemm_mma_kernel<<<dim3(EE / 128, NB * SQ / 128, 3), 256, GEMM_SMEM>>>(
        xf, wth, bq, bk, bv, nullptr, qf, kf, vf,
        SCL2, 1.0f, 1.0f, 1, 0);

    // 4. flash attention (fp16 tensor cores) -> fp16 [n,s,e]
    attn_mma_kernel<<<dim3(SQ / 128, HH, NB), 256, ATT_SMEM>>>(
        qf, kf, vf, mb, aof);

    // 5. out projection -> f32 out
    gemm_mma_kernel<<<dim3(EE / 128, NB * SQ / 128, 1), 256, GEMM_SMEM>>>(
        aof, wth, bo, bo, bo, out,
        nullptr, nullptr, nullptr, 1.0f, 1.0f, 1.0f, 0, 3);
}